// round 6
// baseline (speedup 1.0000x reference)
#include <cuda_runtime.h>

#define B_CHAIN 16384
#define S_SIDE 15
#define NATM (1 + B_CHAIN + B_CHAIN * S_SIDE)
#define GEN1_BASE (1 + B_CHAIN)

#define NBLK 256
#define TPB 256
#define NCHUNK 512            // 32-atom warp chunks over the backbone
#define CHAINS_PER_BLK (B_CHAIN / NBLK)   // 64

// Scratch (static __device__ arrays — no allocation).
__device__ __align__(16) float g_scan[(B_CHAIN + 1) * 12];  // within-chunk inclusive
__device__ __align__(16) float g_blk[NCHUNK * 12];          // chunk totals
__device__ unsigned g_arrive;   // zero-init; self-resetting each launch
__device__ unsigned g_depart;

// Affine 3x4: m[0..8] row-major rotation, m[9..11] translation. c = a*b (a earlier).
__device__ __forceinline__ void aff_mul(const float a[12], const float b[12], float c[12]) {
#pragma unroll
    for (int i = 0; i < 3; i++) {
        float a0 = a[i * 3 + 0], a1 = a[i * 3 + 1], a2 = a[i * 3 + 2];
        float t  = a[9 + i];
        c[i * 3 + 0] = a0 * b[0] + a1 * b[3] + a2 * b[6];
        c[i * 3 + 1] = a0 * b[1] + a1 * b[4] + a2 * b[7];
        c[i * 3 + 2] = a0 * b[2] + a1 * b[5] + a2 * b[8];
        c[9 + i]     = a0 * b[9] + a1 * b[10] + a2 * b[11] + t;
    }
}

__device__ __forceinline__ void aff_identity(float m[12]) {
#pragma unroll
    for (int k = 0; k < 12; k++) m[k] = 0.0f;
    m[0] = m[4] = m[8] = 1.0f;
}

// ht_bond = Rx(p)*Rz(t)*T(d,0,0)*Rx(c), collapsed. Precise trig (backbone).
__device__ __forceinline__ void make_bond(float p, float t, float d, float c, float m[12]) {
    float sp, cp, st, ct, sc, cc;
    sincosf(p, &sp, &cp);
    sincosf(t, &st, &ct);
    sincosf(c, &sc, &cc);
    m[0] = ct;        m[1] = -st * cc;               m[2] = st * sc;
    m[3] = cp * st;   m[4] = cp * ct * cc - sp * sc; m[5] = -cp * ct * sc - sp * cc;
    m[6] = sp * st;   m[7] = sp * ct * cc + cp * sc; m[8] = -sp * ct * sc + cp * cc;
    m[9] = ct * d;    m[10] = cp * st * d;           m[11] = sp * st * d;
}

// Fast-trig variant (side chains: 15-product chains, no accumulation).
__device__ __forceinline__ void make_bond_fast(float p, float t, float d, float c, float m[12]) {
    float sp, cp, st, ct, sc, cc;
    __sincosf(p, &sp, &cp);
    __sincosf(t, &st, &ct);
    __sincosf(c, &sc, &cc);
    m[0] = ct;        m[1] = -st * cc;               m[2] = st * sc;
    m[3] = cp * st;   m[4] = cp * ct * cc - sp * sc; m[5] = -cp * ct * sc - sp * cc;
    m[6] = sp * st;   m[7] = sp * ct * cc + cp * sc; m[8] = -sp * ct * sc + cp * cc;
    m[9] = ct * d;    m[10] = cp * st * d;           m[11] = sp * st * d;
}

__device__ __forceinline__ void make_ht(int atom, float4 dv, float m[12]) {
    if (atom == 1) {   // jump node: T(d0,d1,d2)*Rx(d3)
        float sc, cc;
        sincosf(dv.w, &sc, &cc);
        m[0] = 1.f; m[1] = 0.f; m[2] = 0.f;
        m[3] = 0.f; m[4] = cc;  m[5] = -sc;
        m[6] = 0.f; m[7] = sc;  m[8] = cc;
        m[9] = dv.x; m[10] = dv.y; m[11] = dv.z;
    } else {
        make_bond(dv.x, dv.y, dv.z, dv.w, m);
    }
}

__device__ __forceinline__ void store12(float* dst, const float m[12]) {
    float4* d4 = (float4*)dst;
    d4[0] = make_float4(m[0], m[1], m[2], m[3]);
    d4[1] = make_float4(m[4], m[5], m[6], m[7]);
    d4[2] = make_float4(m[8], m[9], m[10], m[11]);
}

__device__ __forceinline__ void load12(const float* src, float m[12]) {
    const float4* s4 = (const float4*)src;
    float4 a = s4[0], b = s4[1], c = s4[2];
    m[0] = a.x; m[1] = a.y; m[2] = a.z; m[3] = a.w;
    m[4] = b.x; m[5] = b.y; m[6] = b.z; m[7] = b.w;
    m[8] = c.x; m[9] = c.y; m[10] = c.z; m[11] = c.w;
}

// Warp-level inclusive Kogge-Stone (32 lanes), no barriers.
__device__ __forceinline__ void warp_scan32(float P[12], int lane) {
#pragma unroll
    for (int d = 1; d < 32; d <<= 1) {
        float L[12];
#pragma unroll
        for (int k = 0; k < 12; k++)
            L[k] = __shfl_up_sync(0xffffffffu, P[k], d, 32);
        if (lane >= d) {
            float T[12];
            aff_mul(L, P, T);
#pragma unroll
            for (int k = 0; k < 12; k++) P[k] = T[k];
        }
    }
}

// Self-resetting grid barrier (arrive/depart). All blocks call exactly once.
__device__ __forceinline__ void grid_barrier() {
    __syncthreads();
    if (threadIdx.x == 0) {
        __threadfence();
        atomicAdd(&g_arrive, 1u);
        volatile unsigned* va = &g_arrive;
        while (*va < (unsigned)NBLK) { }
        __threadfence();
        unsigned d = atomicAdd(&g_depart, 1u);
        if (d == (unsigned)NBLK - 1u) {   // last out: reset for next launch
            g_arrive = 0u;
            g_depart = 0u;
            __threadfence();
        }
    }
    __syncthreads();
}

// ---------------------------------------------------------------------------
// Single fused persistent kernel. 256 blocks x 256 threads, all co-resident.
// ---------------------------------------------------------------------------
__global__ void __launch_bounds__(TPB, 2) k_fused(const float* __restrict__ dofs,
                                                  const int* __restrict__ kin_id,
                                                  float* __restrict__ out) {
    __shared__ float wt[8 * 12];     // per-warp totals for phase-2 combine
    __shared__ float sPreA[12];      // exclusive prefix for chunk 2b
    __shared__ float sPreB[12];      // exclusive prefix for chunk 2b+1
    int t = threadIdx.x;
    int b = blockIdx.x;
    int w = t >> 5, l = t & 31;

    // ===== Phase 1: backbone chunk scans (blocks 0..63 active) =====
    int gwarp = b * (TPB / 32) + w;     // global warp id
    if (gwarp < NCHUNK) {
        int atom = gwarp * 32 + l + 1;
        float4 dv = ((const float4*)dofs)[atom - 1];
        float P[12];
        make_ht(atom, dv, P);
        warp_scan32(P, l);
        store12(g_scan + atom * 12, P);
        if (l == 31) store12(g_blk + gwarp * 12, P);
    }

    // ===== grid barrier =====
    grid_barrier();

    // ===== Phase 2: redundant prefix of the 512 chunk totals =====
    // Pair product Q_t = blk[2t]*blk[2t+1]; inclusive scan over 256 pairs;
    // block b needs Inc[b-1] (prefix of chunk 2b) and Inc[b-1]*blk[2b].
    {
        float A[12], Bm[12], Q[12];
        load12(g_blk + (2 * t) * 12, A);
        load12(g_blk + (2 * t + 1) * 12, Bm);
        aff_mul(A, Bm, Q);
        warp_scan32(Q, l);
        if (l == 31) {
#pragma unroll
            for (int k = 0; k < 12; k++) wt[w * 12 + k] = Q[k];
        }
        __syncthreads();
        if (w == 0 && l < 8) {          // scan 8 warp totals
            float W[12];
#pragma unroll
            for (int k = 0; k < 12; k++) W[k] = wt[l * 12 + k];
#pragma unroll
            for (int d = 1; d < 8; d <<= 1) {
                float L[12];
#pragma unroll
                for (int k = 0; k < 12; k++)
                    L[k] = __shfl_up_sync(0x000000ffu, W[k], d, 32);
                if (l >= d) {
                    float T[12];
                    aff_mul(L, W, T);
#pragma unroll
                    for (int k = 0; k < 12; k++) W[k] = T[k];
                }
            }
#pragma unroll
            for (int k = 0; k < 12; k++) wt[l * 12 + k] = W[k];
        }
        __syncthreads();
        if (w > 0) {
            float E[12], T[12];
#pragma unroll
            for (int k = 0; k < 12; k++) E[k] = wt[(w - 1) * 12 + k];
            aff_mul(E, Q, T);
#pragma unroll
            for (int k = 0; k < 12; k++) Q[k] = T[k];
        }
        // Q is now Inc[t]. Block needs Inc[b-1].
        if (b == 0) {
            if (t == 0) {
                float I[12];
                aff_identity(I);
#pragma unroll
                for (int k = 0; k < 12; k++) sPreA[k] = I[k];
            }
        } else if (t == b - 1) {
#pragma unroll
            for (int k = 0; k < 12; k++) sPreA[k] = Q[k];
        }
        __syncthreads();
        if (t == 0) {   // prefix for chunk 2b+1 = preA * blk[2b]
            float C0[12], T[12];
            load12(g_blk + (2 * b) * 12, C0);
            float preA[12];
#pragma unroll
            for (int k = 0; k < 12; k++) preA[k] = sPreA[k];
            aff_mul(preA, C0, T);
#pragma unroll
            for (int k = 0; k < 12; k++) sPreB[k] = T[k];
        }
        __syncthreads();
    }

    // ===== Phase 3: rake side chains (64 chains per block, 4 lanes each) =====
    int c = b * CHAINS_PER_BLK + (t >> 2);   // chain id
    int r = t & 3;                            // rake lane

    // first element of this lane
    float E0[12];
    if (r == 0) {
        // parent global = chunkPrefix * g_scan[c+1]; chunk of atom c+1 is c>>5,
        // i.e. 2b (threads t<128) or 2b+1 (t>=128).
        float pre[12], Sv[12];
        const float* ps = (t < 128) ? sPreA : sPreB;
#pragma unroll
        for (int k = 0; k < 12; k++) pre[k] = ps[k];
        load12(g_scan + (c + 1) * 12, Sv);
        aff_mul(pre, Sv, E0);
    } else {
        int node = GEN1_BASE + c * S_SIDE + (4 * r - 1);
        float4 dv = ((const float4*)dofs)[node - 1];
        make_bond_fast(dv.x, dv.y, dv.z, dv.w, E0);
    }

    // phase 3a: dense serial local product
    float P[12];
#pragma unroll
    for (int k = 0; k < 12; k++) P[k] = E0[k];
#pragma unroll
    for (int j = 1; j < 4; j++) {
        int node = GEN1_BASE + c * S_SIDE + (4 * r + j - 1);
        float4 dv = ((const float4*)dofs)[node - 1];
        float M[12], T[12];
        make_bond_fast(dv.x, dv.y, dv.z, dv.w, M);
        aff_mul(P, M, T);
#pragma unroll
        for (int k = 0; k < 12; k++) P[k] = T[k];
    }

    // phase 3b: width-4 inclusive scan (2 steps)
#pragma unroll
    for (int d = 1; d < 4; d <<= 1) {
        float L[12];
#pragma unroll
        for (int k = 0; k < 12; k++)
            L[k] = __shfl_up_sync(0xffffffffu, P[k], d, 4);
        if (r >= d) {
            float T[12];
            aff_mul(L, P, T);
#pragma unroll
            for (int k = 0; k < 12; k++) P[k] = T[k];
        }
    }

    // exclusive prefix for this lane
    float X[12];
#pragma unroll
    for (int k = 0; k < 12; k++) X[k] = __shfl_up_sync(0xffffffffu, P[k], 1, 4);
    if (r == 0) aff_identity(X);

    // phase 3c: apply + emit 4 prefix translations
    float G[12];
    {
        float T[12];
        aff_mul(X, E0, T);
#pragma unroll
        for (int k = 0; k < 12; k++) G[k] = T[k];
    }
    {
        int node = (r == 0) ? (c + 1) : (GEN1_BASE + c * S_SIDE + (4 * r - 1));
        int kid = kin_id[node];
        out[kid * 3 + 0] = G[9];
        out[kid * 3 + 1] = G[10];
        out[kid * 3 + 2] = G[11];
    }
#pragma unroll
    for (int j = 1; j < 4; j++) {
        int node = GEN1_BASE + c * S_SIDE + (4 * r + j - 1);
        float4 dv = ((const float4*)dofs)[node - 1];
        float M[12], T[12];
        make_bond_fast(dv.x, dv.y, dv.z, dv.w, M);
        aff_mul(G, M, T);
#pragma unroll
        for (int k = 0; k < 12; k++) G[k] = T[k];
        int kid = kin_id[node];
        out[kid * 3 + 0] = G[9];
        out[kid * 3 + 1] = G[10];
        out[kid * 3 + 2] = G[11];
    }
}

extern "C" void kernel_launch(void* const* d_in, const int* in_sizes, int n_in,
                              void* d_out, int out_size) {
    const float* dofs   = (const float*)d_in[0];
    const int*   kin_id = (const int*)d_in[8];
    float*       out    = (float*)d_out;

    k_fused<<<NBLK, TPB>>>(dofs, kin_id, out);
}